// round 4
// baseline (speedup 1.0000x reference)
#include <cuda_runtime.h>
#include <cuda_bf16.h>
#include <cstdint>

// ---------------------------------------------------------------------------
// KimiDeltaAttention — fp32 baseline with packed f32x2 FMA (Blackwell FFMA2)
// B=4, T=2048, HID=2048, H=16, DK=DV=128
// Scratch buffers are __device__ globals resolved INSIDE kernels (by id), so
// kernel_launch performs kernel launches only — nothing else during capture.
// ---------------------------------------------------------------------------

#define Bc 4
#define Tc 2048
#define HIDc 2048
#define Hc 16
#define DKc 128
#define DVc 128
#define Mc (Bc * Tc)            // 8192 rows

typedef unsigned long long ull;

// ------------------------- scratch (device globals) ------------------------
__device__ float g_q   [(size_t)Mc * HIDc];
__device__ float g_k   [(size_t)Mc * HIDc];
__device__ float g_v   [(size_t)Mc * HIDc];
__device__ float g_eg  [(size_t)Mc * HIDc];   // exp(gate)
__device__ float g_sigf[(size_t)Mc * HIDc];   // sigmoid(factor)
__device__ float g_o   [(size_t)Mc * HIDc];
__device__ float g_og  [(size_t)Mc * HIDc];
__device__ float g_tmp [(size_t)Mc * 128];    // low-rank intermediate (f / gf)
__device__ float g_beta[(size_t)Mc * Hc];

#define ID_Q    0
#define ID_K    1
#define ID_V    2
#define ID_EG   3
#define ID_SIGF 4
#define ID_O    5
#define ID_OG   6
#define ID_TMP  7
#define ID_BETA 8

__device__ __forceinline__ float* scratch_resolve(int id) {
    switch (id) {
        case ID_Q:    return g_q;
        case ID_K:    return g_k;
        case ID_V:    return g_v;
        case ID_EG:   return g_eg;
        case ID_SIGF: return g_sigf;
        case ID_O:    return g_o;
        case ID_OG:   return g_og;
        case ID_TMP:  return g_tmp;
        default:      return g_beta;
    }
}

// ------------------------------ f32x2 helpers ------------------------------
__device__ __forceinline__ ull f2pack(float a, float b) {
    ull r; asm("mov.b64 %0, {%1, %2};" : "=l"(r) : "f"(a), "f"(b)); return r;
}
__device__ __forceinline__ float2 f2unpack(ull x) {
    float2 r; asm("mov.b64 {%0, %1}, %2;" : "=f"(r.x), "=f"(r.y) : "l"(x)); return r;
}
__device__ __forceinline__ ull ffma2(ull a, ull b, ull c) {
    ull d; asm("fma.rn.f32x2 %0, %1, %2, %3;" : "=l"(d) : "l"(a), "l"(b), "l"(c)); return d;
}
__device__ __forceinline__ ull fmul2(ull a, ull b) {
    ull d; asm("mul.rn.f32x2 %0, %1, %2;" : "=l"(d) : "l"(a), "l"(b)); return d;
}

__device__ __forceinline__ void cp16(void* s, const void* g) {
    unsigned sa = (unsigned)__cvta_generic_to_shared(s);
    asm volatile("cp.async.ca.shared.global [%0], [%1], 16;" :: "r"(sa), "l"(g));
}
__device__ __forceinline__ void cp4(void* s, const void* g) {
    unsigned sa = (unsigned)__cvta_generic_to_shared(s);
    asm volatile("cp.async.ca.shared.global [%0], [%1], 4;" :: "r"(sa), "l"(g));
}
__device__ __forceinline__ void cp_commit() { asm volatile("cp.async.commit_group;"); }
__device__ __forceinline__ void cp_wait2()  { asm volatile("cp.async.wait_group 2;"); }

// -------------------------------- SGEMM ------------------------------------
// C[M,N] = act( A[M,K] @ W[N,K]^T ), all row-major. BM=BN=128, BK=8,
// 256 threads, 8x8 per thread, f32x2 accumulators, double-buffered smem.
// ACT: 0 none | 1 silu | 2 kda-gate->exp | 3 sigmoid(x + aux1[n])
// A is harness input if Aid<0 (use Aext), else scratch id. C always scratch id
// unless Cid<0 (then Cext).
#define BM 128
#define BN 128
#define BK 8
#define PAD 4

template <int ACT>
__global__ __launch_bounds__(256) void sgemm_kernel(
    const float* __restrict__ Aext, int Aid,
    float* __restrict__ Cext, int Cid,
    int M, int N, int K,
    const float* __restrict__ W,
    const float* __restrict__ aux1, const float* __restrict__ aux2)
{
    const float* A = (Aid >= 0) ? scratch_resolve(Aid) : Aext;
    float*       C = (Cid >= 0) ? scratch_resolve(Cid) : Cext;

    __shared__ float As[2][BK][BM + PAD];
    __shared__ float Ws[2][BK][BN + PAD];

    const int tid = threadIdx.x;
    const int bm = blockIdx.y, bn = blockIdx.x;
    const float* Ab = A + (size_t)bm * BM * K;
    const float* Wb = W + (size_t)bn * BN * K;

    const int lrow = tid >> 1;          // 0..127
    const int lk4  = (tid & 1) * 4;     // 0 or 4

    const int ty = tid >> 4, tx = tid & 15;
    const int m0 = ty * 8, n0 = tx * 8;

    ull acc[8][4];
#pragma unroll
    for (int i = 0; i < 8; i++)
#pragma unroll
        for (int j = 0; j < 4; j++) acc[i][j] = 0ull;

    // prologue: stage 0
    {
        float4 a0 = *(const float4*)(Ab + (size_t)lrow * K + lk4);
        float4 w0 = *(const float4*)(Wb + (size_t)lrow * K + lk4);
        As[0][lk4 + 0][lrow] = a0.x; As[0][lk4 + 1][lrow] = a0.y;
        As[0][lk4 + 2][lrow] = a0.z; As[0][lk4 + 3][lrow] = a0.w;
        Ws[0][lk4 + 0][lrow] = w0.x; Ws[0][lk4 + 1][lrow] = w0.y;
        Ws[0][lk4 + 2][lrow] = w0.z; Ws[0][lk4 + 3][lrow] = w0.w;
    }
    __syncthreads();

    const int nkt = K / BK;
    int buf = 0;
    for (int kt = 0; kt < nkt; kt++) {
        float4 an, wn;
        const bool has = (kt + 1 < nkt);
        if (has) {
            size_t go = (size_t)lrow * K + (size_t)(kt + 1) * BK + lk4;
            an = *(const float4*)(Ab + go);
            wn = *(const float4*)(Wb + go);
        }
#pragma unroll
        for (int kk = 0; kk < BK; kk++) {
            float4 aA = *(const float4*)&As[buf][kk][m0];
            float4 aB = *(const float4*)&As[buf][kk][m0 + 4];
            ull b0 = *(const ull*)&Ws[buf][kk][n0];
            ull b1 = *(const ull*)&Ws[buf][kk][n0 + 2];
            ull b2 = *(const ull*)&Ws[buf][kk][n0 + 4];
            ull b3 = *(const ull*)&Ws[buf][kk][n0 + 6];
            float av[8] = {aA.x, aA.y, aA.z, aA.w, aB.x, aB.y, aB.z, aB.w};
#pragma unroll
            for (int i = 0; i < 8; i++) {
                ull ap = f2pack(av[i], av[i]);
                acc[i][0] = ffma2(ap, b0, acc[i][0]);
                acc[i][1] = ffma2(ap, b1, acc[i][1]);
                acc[i][2] = ffma2(ap, b2, acc[i][2]);
                acc[i][3] = ffma2(ap, b3, acc[i][3]);
            }
        }
        if (has) {
            int nb = buf ^ 1;
            As[nb][lk4 + 0][lrow] = an.x; As[nb][lk4 + 1][lrow] = an.y;
            As[nb][lk4 + 2][lrow] = an.z; As[nb][lk4 + 3][lrow] = an.w;
            Ws[nb][lk4 + 0][lrow] = wn.x; Ws[nb][lk4 + 1][lrow] = wn.y;
            Ws[nb][lk4 + 2][lrow] = wn.z; Ws[nb][lk4 + 3][lrow] = wn.w;
        }
        __syncthreads();
        buf ^= 1;
    }

    // epilogue
    const int gn0 = bn * BN + n0;
#pragma unroll
    for (int i = 0; i < 8; i++) {
        const int gm = bm * BM + m0 + i;
        float out[8];
#pragma unroll
        for (int j = 0; j < 4; j++) {
            float2 c = f2unpack(acc[i][j]);
            out[2 * j] = c.x; out[2 * j + 1] = c.y;
        }
#pragma unroll
        for (int jj = 0; jj < 8; jj++) {
            float x = out[jj];
            const int n = gn0 + jj;
            if (ACT == 1) {                 // silu
                x = x / (1.0f + expf(-x));
            } else if (ACT == 2) {          // kda gate -> store exp(g)
                float a  = expf(aux1[n >> 7]);       // exp(A_log[h])
                float sp = x + aux2[n];              // + dt_bias
                sp = (sp > 20.0f) ? sp : log1pf(expf(sp));
                x = expf(-a * sp);
            } else if (ACT == 3) {          // sigmoid(x + g_b1[n])
                x = 1.0f / (1.0f + expf(-(x + aux1[n])));
            }
            out[jj] = x;
        }
        float4* cp0 = (float4*)(C + (size_t)gm * N + gn0);
        cp0[0] = make_float4(out[0], out[1], out[2], out[3]);
        cp0[1] = make_float4(out[4], out[5], out[6], out[7]);
    }
}

// --------------------------- beta = sigmoid(h @ b_w^T) ---------------------
__global__ __launch_bounds__(512) void beta_kernel(
    const float* __restrict__ H, const float* __restrict__ BW)
{
    float* BETA = scratch_resolve(ID_BETA);
    const int m = blockIdx.x;
    const int w = threadIdx.x >> 5, lane = threadIdx.x & 31;
    const float4* hr = (const float4*)(H + (size_t)m * HIDc);
    const float4* br = (const float4*)(BW + (size_t)w * HIDc);
    float s = 0.f;
#pragma unroll 4
    for (int i = lane; i < HIDc / 4; i += 32) {
        float4 a = hr[i], b = br[i];
        s += a.x * b.x + a.y * b.y + a.z * b.z + a.w * b.w;
    }
#pragma unroll
    for (int off = 16; off > 0; off >>= 1)
        s += __shfl_xor_sync(0xffffffffu, s, off);
    if (lane == 0) BETA[(size_t)m * Hc + w] = 1.0f / (1.0f + expf(-s));
}

// --------------------------- per-head L2 norm (in place) -------------------
__global__ __launch_bounds__(128) void l2norm_kernel(int Xid, float scale)
{
    float* X = scratch_resolve(Xid);
    const int h = blockIdx.x, m = blockIdx.y;
    const int v = threadIdx.x;
    const size_t off = (size_t)m * HIDc + (size_t)h * DKc + v;
    float x = X[off];
    float s = x * x;
#pragma unroll
    for (int o = 16; o > 0; o >>= 1) s += __shfl_xor_sync(0xffffffffu, s, o);
    __shared__ float red[4];
    if ((v & 31) == 0) red[v >> 5] = s;
    __syncthreads();
    float tot = red[0] + red[1] + red[2] + red[3];
    X[off] = x * rsqrtf(tot + 1e-6f) * scale;
}

// ------------------- gated RMS norm: og = rms(o)*w*sigf --------------------
__global__ __launch_bounds__(128) void gate_kernel(const float* __restrict__ NW)
{
    const float* O    = scratch_resolve(ID_O);
    const float* SIGF = scratch_resolve(ID_SIGF);
    float*       OG   = scratch_resolve(ID_OG);
    const int h = blockIdx.x, m = blockIdx.y;
    const int v = threadIdx.x;
    const size_t off = (size_t)m * HIDc + (size_t)h * DVc + v;
    float x = O[off];
    float s = x * x;
#pragma unroll
    for (int o = 16; o > 0; o >>= 1) s += __shfl_xor_sync(0xffffffffu, s, o);
    __shared__ float red[4];
    if ((v & 31) == 0) red[v >> 5] = s;
    __syncthreads();
    float tot = red[0] + red[1] + red[2] + red[3];
    float r = rsqrtf(tot * (1.0f / DVc) + 1e-5f);
    OG[off] = x * r * NW[v] * SIGF[off];
}

// ------------------------------ recurrent scan -----------------------------
// grid (2, H, B); 128 threads. CTA owns 64 v-columns; thread pair (shfl xor 1)
// splits the 128-k dim. State kept as 32 f32x2 pairs per thread.
__global__ __launch_bounds__(128) void scan_kernel(
    const float* __restrict__ S0,
    float* __restrict__ Sout, int writeS)
{
    const float* Q    = scratch_resolve(ID_Q);
    const float* K    = scratch_resolve(ID_K);
    const float* V    = scratch_resolve(ID_V);
    const float* EG   = scratch_resolve(ID_EG);
    const float* BETA = scratch_resolve(ID_BETA);
    float*       O    = scratch_resolve(ID_O);

    const int vh = blockIdx.x, h = blockIdx.y, b = blockIdx.z;
    const int tid = threadIdx.x;
    const int vloc = tid >> 1, khalf = tid & 1;
    const int v = vh * 64 + vloc;
    const int ks = khalf * 64;

    __shared__ float sbuf[3][4][128];   // [stage][k,q,v,eg][128]
    __shared__ float sbeta[3];

    const size_t rowbase = (size_t)b * Tc * HIDc + (size_t)h * DKc;

    // init state from S0[b,h,k,v]
    ull S[32];
    {
        const float* s0p = S0 + (((size_t)(b * Hc + h) * DKc + ks) * DVc + v);
#pragma unroll
        for (int j2 = 0; j2 < 32; j2++)
            S[j2] = f2pack(s0p[(size_t)(2 * j2) * DVc], s0p[(size_t)(2 * j2 + 1) * DVc]);
    }

    const int grp = tid >> 5, lane = tid & 31;
    const float* srcs[4] = {K, Q, V, EG};

    // prologue: prefetch t=0,1
#pragma unroll
    for (int t = 0; t < 2; t++) {
        size_t off = rowbase + (size_t)t * HIDc;
        cp16(&sbuf[t][grp][lane * 4], srcs[grp] + off + lane * 4);
        if (tid == 0) cp4(&sbeta[t], BETA + ((size_t)(b * Tc + t)) * Hc + h);
        cp_commit();
    }

    for (int t = 0; t < Tc; t++) {
        const int nt = t + 2;
        if (nt < Tc) {
            const int st = nt % 3;
            size_t off = rowbase + (size_t)nt * HIDc;
            cp16(&sbuf[st][grp][lane * 4], srcs[grp] + off + lane * 4);
            if (tid == 0) cp4(&sbeta[st], BETA + ((size_t)(b * Tc + nt)) * Hc + h);
        }
        cp_commit();
        cp_wait2();
        __syncthreads();

        const int cb = t % 3;
        const float beta = sbeta[cb];
        const float vv = sbuf[cb][2][v];

        ull k2[32];
        ull kv2 = 0ull;
#pragma unroll
        for (int j2 = 0; j2 < 32; j2++) {
            k2[j2]   = *(const ull*)&sbuf[cb][0][ks + 2 * j2];
            ull eg2  = *(const ull*)&sbuf[cb][3][ks + 2 * j2];
            S[j2] = fmul2(S[j2], eg2);
            kv2 = ffma2(k2[j2], S[j2], kv2);
        }
        float2 kvp = f2unpack(kv2);
        float kv = kvp.x + kvp.y;
        kv += __shfl_xor_sync(0xffffffffu, kv, 1);

        const float delta = (vv - kv) * beta;
        const ull d2 = f2pack(delta, delta);

        ull o2 = 0ull;
#pragma unroll
        for (int j2 = 0; j2 < 32; j2++) {
            S[j2] = ffma2(k2[j2], d2, S[j2]);
            ull q2 = *(const ull*)&sbuf[cb][1][ks + 2 * j2];
            o2 = ffma2(q2, S[j2], o2);
        }
        float2 op = f2unpack(o2);
        float o = op.x + op.y;
        o += __shfl_xor_sync(0xffffffffu, o, 1);
        if (khalf == 0)
            O[rowbase + (size_t)t * HIDc + v] = o;
        __syncthreads();
    }

    if (writeS) {
        float* sp = Sout + (((size_t)(b * Hc + h) * DKc + ks) * DVc + v);
#pragma unroll
        for (int j2 = 0; j2 < 32; j2++) {
            float2 c = f2unpack(S[j2]);
            sp[(size_t)(2 * j2) * DVc]     = c.x;
            sp[(size_t)(2 * j2 + 1) * DVc] = c.y;
        }
    }
}

// ------------------------------ host launcher ------------------------------
extern "C" void kernel_launch(void* const* d_in, const int* in_sizes, int n_in,
                              void* d_out, int out_size)
{
    const float* h      = (const float*)d_in[0];
    const float* S0     = (const float*)d_in[1];
    const float* q_w    = (const float*)d_in[2];
    const float* k_w    = (const float*)d_in[3];
    const float* v_w    = (const float*)d_in[4];
    const float* f_w0   = (const float*)d_in[5];
    const float* f_w1   = (const float*)d_in[6];
    const float* b_w    = (const float*)d_in[7];
    const float* A_log  = (const float*)d_in[8];
    const float* dt_b   = (const float*)d_in[9];
    const float* g_w0   = (const float*)d_in[10];
    const float* g_w1   = (const float*)d_in[11];
    const float* g_b1   = (const float*)d_in[12];
    const float* o_nw   = (const float*)d_in[13];
    const float* o_w    = (const float*)d_in[14];
    float* out = (float*)d_out;

    const dim3 blk(256);
    const dim3 g_big(HIDc / BN, Mc / BM);   // (16, 64)
    const dim3 g_n128(1, Mc / BM);          // (1, 64)

    // projections (silu fused)
    sgemm_kernel<1><<<g_big,  blk>>>(h, -1, nullptr, ID_Q, Mc, HIDc, HIDc, q_w, nullptr, nullptr);
    sgemm_kernel<1><<<g_big,  blk>>>(h, -1, nullptr, ID_K, Mc, HIDc, HIDc, k_w, nullptr, nullptr);
    sgemm_kernel<1><<<g_big,  blk>>>(h, -1, nullptr, ID_V, Mc, HIDc, HIDc, v_w, nullptr, nullptr);

    // gate: f = h @ f_w0^T ; eg = exp(-exp(A_log)*softplus(f @ f_w1^T + dt_bias))
    sgemm_kernel<0><<<g_n128, blk>>>(h, -1, nullptr, ID_TMP, Mc, 128, HIDc, f_w0, nullptr, nullptr);
    sgemm_kernel<2><<<g_big,  blk>>>(nullptr, ID_TMP, nullptr, ID_EG, Mc, HIDc, 128, f_w1, A_log, dt_b);

    // beta
    beta_kernel<<<Mc, 512>>>(h, b_w);

    // l2 norm q (with 1/sqrt(DK) folded) and k
    l2norm_kernel<<<dim3(Hc, Mc), 128>>>(ID_Q, 0.08838834764831845f);
    l2norm_kernel<<<dim3(Hc, Mc), 128>>>(ID_K, 1.0f);

    // output gate factor: sigf = sigmoid((h @ g_w0^T) @ g_w1^T + g_b1)
    sgemm_kernel<0><<<g_n128, blk>>>(h, -1, nullptr, ID_TMP, Mc, 128, HIDc, g_w0, nullptr, nullptr);
    sgemm_kernel<3><<<g_big,  blk>>>(nullptr, ID_TMP, nullptr, ID_SIGF, Mc, HIDc, 128, g_w1, g_b1, nullptr);

    // recurrent scan
    const size_t out_elems = (size_t)Mc * HIDc;                 // 16,777,216
    const size_t s_elems   = (size_t)Bc * Hc * DKc * DVc;       //  1,048,576
    const int writeS = ((size_t)out_size >= out_elems + s_elems) ? 1 : 0;
    scan_kernel<<<dim3(2, Hc, Bc), 128>>>(S0, out + out_elems, writeS);

    // gated rms norm + final projection
    gate_kernel<<<dim3(Hc, Mc), 128>>>(o_nw);
    sgemm_kernel<0><<<g_big,  blk>>>(nullptr, ID_OG, out, -1, Mc, HIDc, HIDc, o_w, nullptr, nullptr);
}

// round 6
// speedup vs baseline: 1.9054x; 1.9054x over previous
#include <cuda_runtime.h>
#include <cuda_bf16.h>
#include <cstdint>

// ---------------------------------------------------------------------------
// KimiDeltaAttention — mma.sync bf16-split GEMMs (fp32-accurate) + fp32 scan
// B=4, T=2048, HID=2048, H=16, DK=DV=128
// NOTE: harness compiles PTX at compute_103 (no 'a' features) -> tcgen05 is
// unavailable; tensor path uses mma.sync.m16n8k16 bf16 (HMMA).
// ---------------------------------------------------------------------------

#define Bc 4
#define Tc 2048
#define HIDc 2048
#define Hc 16
#define DKc 128
#define DVc 128
#define Mc (Bc * Tc)            // 8192 rows

typedef unsigned long long ull;
typedef unsigned int u32;

// ------------------------- fp32 scratch (device globals) -------------------
__device__ float g_q   [(size_t)Mc * HIDc];
__device__ float g_k   [(size_t)Mc * HIDc];
__device__ float g_v   [(size_t)Mc * HIDc];
__device__ float g_eg  [(size_t)Mc * HIDc];   // exp(gate)
__device__ float g_sigf[(size_t)Mc * HIDc];   // sigmoid(factor)
__device__ float g_o   [(size_t)Mc * HIDc];
__device__ float g_tmp [(size_t)Mc * 128];    // low-rank intermediate
__device__ float g_beta[(size_t)Mc * Hc];

#define ID_Q    0
#define ID_K    1
#define ID_V    2
#define ID_EG   3
#define ID_SIGF 4
#define ID_O    5
#define ID_TMP  6
#define ID_BETA 7

__device__ __forceinline__ float* scratch_resolve(int id) {
    switch (id) {
        case ID_Q:    return g_q;
        case ID_K:    return g_k;
        case ID_V:    return g_v;
        case ID_EG:   return g_eg;
        case ID_SIGF: return g_sigf;
        case ID_O:    return g_o;
        case ID_TMP:  return g_tmp;
        default:      return g_beta;
    }
}

// ------------------------- bf16 split pool ---------------------------------
constexpr size_t OFF_HB_HI  = 0;
constexpr size_t OFF_HB_LO  = OFF_HB_HI  + (size_t)Mc * HIDc;
constexpr size_t OFF_WQ_HI  = OFF_HB_LO  + (size_t)Mc * HIDc;
constexpr size_t OFF_WQ_LO  = OFF_WQ_HI  + (size_t)HIDc * HIDc;
constexpr size_t OFF_WK_HI  = OFF_WQ_LO  + (size_t)HIDc * HIDc;
constexpr size_t OFF_WK_LO  = OFF_WK_HI  + (size_t)HIDc * HIDc;
constexpr size_t OFF_WV_HI  = OFF_WK_LO  + (size_t)HIDc * HIDc;
constexpr size_t OFF_WV_LO  = OFF_WV_HI  + (size_t)HIDc * HIDc;
constexpr size_t OFF_WO_HI  = OFF_WV_LO  + (size_t)HIDc * HIDc;
constexpr size_t OFF_WO_LO  = OFF_WO_HI  + (size_t)HIDc * HIDc;
constexpr size_t OFF_FW0_HI = OFF_WO_LO  + (size_t)HIDc * HIDc;
constexpr size_t OFF_FW0_LO = OFF_FW0_HI + (size_t)128 * HIDc;
constexpr size_t OFF_GW0_HI = OFF_FW0_LO + (size_t)128 * HIDc;
constexpr size_t OFF_GW0_LO = OFF_GW0_HI + (size_t)128 * HIDc;
constexpr size_t OFF_FW1_HI = OFF_GW0_LO + (size_t)128 * HIDc;
constexpr size_t OFF_FW1_LO = OFF_FW1_HI + (size_t)HIDc * 128;
constexpr size_t OFF_GW1_HI = OFF_FW1_LO + (size_t)HIDc * 128;
constexpr size_t OFF_GW1_LO = OFF_GW1_HI + (size_t)HIDc * 128;
constexpr size_t OFF_TMP_HI = OFF_GW1_LO + (size_t)HIDc * 128;
constexpr size_t OFF_TMP_LO = OFF_TMP_HI + (size_t)Mc * 128;
constexpr size_t OFF_OG_HI  = OFF_TMP_LO + (size_t)Mc * 128;
constexpr size_t OFF_OG_LO  = OFF_OG_HI  + (size_t)Mc * HIDc;
constexpr size_t BF_TOTAL   = OFF_OG_LO  + (size_t)Mc * HIDc;

__device__ __nv_bfloat16 g_bfpool[BF_TOTAL];

// ------------------------------ f32x2 helpers ------------------------------
__device__ __forceinline__ ull f2pack(float a, float b) {
    ull r; asm("mov.b64 %0, {%1, %2};" : "=l"(r) : "f"(a), "f"(b)); return r;
}
__device__ __forceinline__ float2 f2unpack(ull x) {
    float2 r; asm("mov.b64 {%0, %1}, %2;" : "=f"(r.x), "=f"(r.y) : "l"(x)); return r;
}
__device__ __forceinline__ ull ffma2(ull a, ull b, ull c) {
    ull d; asm("fma.rn.f32x2 %0, %1, %2, %3;" : "=l"(d) : "l"(a), "l"(b), "l"(c)); return d;
}
__device__ __forceinline__ ull fmul2(ull a, ull b) {
    ull d; asm("mul.rn.f32x2 %0, %1, %2;" : "=l"(d) : "l"(a), "l"(b)); return d;
}

// ------------------------------ async copy ---------------------------------
__device__ __forceinline__ void cp16(void* s, const void* g) {
    u32 sa = (u32)__cvta_generic_to_shared(s);
    asm volatile("cp.async.ca.shared.global [%0], [%1], 16;" :: "r"(sa), "l"(g));
}
__device__ __forceinline__ void cp16u(u32 s, const void* g) {
    asm volatile("cp.async.cg.shared.global [%0], [%1], 16;" :: "r"(s), "l"(g));
}
__device__ __forceinline__ void cp4(void* s, const void* g) {
    u32 sa = (u32)__cvta_generic_to_shared(s);
    asm volatile("cp.async.ca.shared.global [%0], [%1], 4;" :: "r"(sa), "l"(g));
}
__device__ __forceinline__ void cp_commit() { asm volatile("cp.async.commit_group;"); }
__device__ __forceinline__ void cp_wait2()  { asm volatile("cp.async.wait_group 2;"); }

__device__ __forceinline__ u32 smem_u32(const void* p) {
    return (u32)__cvta_generic_to_shared(p);
}

// ------------------------------ mma helpers --------------------------------
__device__ __forceinline__ void mma16816(float* c, const u32* a, const u32* b) {
    asm volatile(
        "mma.sync.aligned.m16n8k16.row.col.f32.bf16.bf16.f32 "
        "{%0,%1,%2,%3}, {%4,%5,%6,%7}, {%8,%9}, {%0,%1,%2,%3};"
        : "+f"(c[0]), "+f"(c[1]), "+f"(c[2]), "+f"(c[3])
        : "r"(a[0]), "r"(a[1]), "r"(a[2]), "r"(a[3]), "r"(b[0]), "r"(b[1]));
}
__device__ __forceinline__ void ldsm4(u32* r, u32 addr) {
    asm volatile("ldmatrix.sync.aligned.m8n8.x4.shared.b16 {%0,%1,%2,%3}, [%4];"
        : "=r"(r[0]), "=r"(r[1]), "=r"(r[2]), "=r"(r[3]) : "r"(addr));
}

// ------------------------------ split kernel -------------------------------
__global__ __launch_bounds__(256) void split_kernel(
    const float* __restrict__ ext, int srcId, size_t off_hi, size_t off_lo)
{
    const float* src = (srcId >= 0) ? scratch_resolve(srcId) : ext;
    size_t i = ((size_t)blockIdx.x * 256 + threadIdx.x) * 4;
    float4 x = *(const float4*)(src + i);
    __nv_bfloat16 h0 = __float2bfloat16(x.x), h1 = __float2bfloat16(x.y);
    __nv_bfloat16 h2 = __float2bfloat16(x.z), h3 = __float2bfloat16(x.w);
    __nv_bfloat16 l0 = __float2bfloat16(x.x - __bfloat162float(h0));
    __nv_bfloat16 l1 = __float2bfloat16(x.y - __bfloat162float(h1));
    __nv_bfloat16 l2 = __float2bfloat16(x.z - __bfloat162float(h2));
    __nv_bfloat16 l3 = __float2bfloat16(x.w - __bfloat162float(h3));
    uint2 ph, pl;
    ph.x = (u32)__bfloat16_as_ushort(h0) | ((u32)__bfloat16_as_ushort(h1) << 16);
    ph.y = (u32)__bfloat16_as_ushort(h2) | ((u32)__bfloat16_as_ushort(h3) << 16);
    pl.x = (u32)__bfloat16_as_ushort(l0) | ((u32)__bfloat16_as_ushort(l1) << 16);
    pl.y = (u32)__bfloat16_as_ushort(l2) | ((u32)__bfloat16_as_ushort(l3) << 16);
    *(uint2*)(g_bfpool + off_hi + i) = ph;
    *(uint2*)(g_bfpool + off_lo + i) = pl;
}

// ------------------------- mma.sync split-bf16 GEMM ------------------------
// C[M,N] = act( A[M,K] @ W[N,K]^T ), fp32-accurate:
//   D += Ahi*Whi + Ahi*Wlo + Alo*Whi  (fp32 accumulators)
// CTA tile 128x128, 256 thr (8 warps, 2x4; warp tile 64x32), BK=32, 2-stage
// cp.async pipeline, XOR-swizzled smem, ldmatrix fragment loads.
// ACT: 0 none | 1 silu | 2 kda-gate->exp | 3 sigmoid(x+aux1[n])
constexpr int BKg         = 32;
constexpr int TILE_BYTES  = 128 * BKg * 2;     // 8 KB
constexpr int STAGE_BYTES = 4 * TILE_BYTES;    // 32 KB
constexpr int GSMEM       = 2 * STAGE_BYTES;   // 64 KB

template <int ACT>
__global__ __launch_bounds__(256) void mma_gemm(
    size_t a_hi, size_t a_lo, size_t w_hi, size_t w_lo,
    float* __restrict__ Cext, int Cid, int Ntot, int Ktot,
    const float* __restrict__ aux1, const float* __restrict__ aux2)
{
    extern __shared__ char dsm[];
    const u32 sb = smem_u32(dsm);
    const int tid = threadIdx.x, lane = tid & 31, wid = tid >> 5;
    const int warp_m = wid & 1, warp_n = wid >> 1;    // 2 x 4 warp grid
    const int bm = blockIdx.y, bn = blockIdx.x;

    const __nv_bfloat16* srcs[4] = {
        g_bfpool + a_hi + (size_t)bm * 128 * Ktot,
        g_bfpool + a_lo + (size_t)bm * 128 * Ktot,
        g_bfpool + w_hi + (size_t)bn * 128 * Ktot,
        g_bfpool + w_lo + (size_t)bn * 128 * Ktot };

    float acc[4][4][4];
#pragma unroll
    for (int i = 0; i < 4; i++)
#pragma unroll
        for (int j = 0; j < 4; j++)
#pragma unroll
            for (int e = 0; e < 4; e++) acc[i][j][e] = 0.f;

    const int NC = Ktot / BKg;

    // per-thread ldmatrix lane geometry
    const int jq = lane >> 3, rq = lane & 7;
    const int jlow = jq & 1, jhi = jq >> 1;

    // --- stage loader: 4 tiles x 128 rows x 4 x 16B groups, swizzled
    auto load_stage = [&](int stage, int c) {
        u32 base = sb + (u32)stage * STAGE_BYTES;
#pragma unroll
        for (int t = 0; t < 4; t++) {
            const __nv_bfloat16* src = srcs[t] + (size_t)c * BKg;
            u32 tb = base + (u32)t * TILE_BYTES;
#pragma unroll
            for (int i = 0; i < 2; i++) {
                int idx = tid + i * 256;                 // 0..511
                u32 row = (u32)(idx >> 2), g = (u32)(idx & 3);
                u32 so = tb + row * 64u + ((g ^ (row & 3u)) * 16u);
                cp16u(so, (const char*)(src + (size_t)row * Ktot) + g * 16);
            }
        }
    };

    load_stage(0, 0); cp_commit();

    for (int c = 0; c < NC; c++) {
        if (c + 1 < NC) {
            load_stage((c + 1) & 1, c + 1); cp_commit();
            asm volatile("cp.async.wait_group 1;" ::: "memory");
        } else {
            asm volatile("cp.async.wait_group 0;" ::: "memory");
        }
        __syncthreads();

        const u32 base = sb + (u32)(c & 1) * STAGE_BYTES;
        const u32 ah = base, al = base + TILE_BYTES;
        const u32 wh = base + 2 * TILE_BYTES, wl = base + 3 * TILE_BYTES;

#pragma unroll
        for (int ks = 0; ks < 2; ks++) {
            const u32 g = (u32)(ks * 2 + jhi);
            u32 a_hi_f[4][4], a_lo_f[4][4];
#pragma unroll
            for (int mi = 0; mi < 4; mi++) {
                u32 row = (u32)(warp_m * 64 + mi * 16 + jlow * 8 + rq);
                u32 off = row * 64u + ((g ^ (row & 3u)) * 16u);
                ldsm4(a_hi_f[mi], ah + off);
                ldsm4(a_lo_f[mi], al + off);
            }
            u32 b_hi_f[4][2], b_lo_f[4][2];
#pragma unroll
            for (int pi = 0; pi < 2; pi++) {
                u32 row = (u32)(warp_n * 32 + pi * 16 + jlow * 8 + rq);
                u32 off = row * 64u + ((g ^ (row & 3u)) * 16u);
                u32 t0[4], t1[4];
                ldsm4(t0, wh + off);
                ldsm4(t1, wl + off);
                b_hi_f[2*pi][0] = t0[0]; b_hi_f[2*pi][1] = t0[2];
                b_hi_f[2*pi+1][0] = t0[1]; b_hi_f[2*pi+1][1] = t0[3];
                b_lo_f[2*pi][0] = t1[0]; b_lo_f[2*pi][1] = t1[2];
                b_lo_f[2*pi+1][0] = t1[1]; b_lo_f[2*pi+1][1] = t1[3];
            }
#pragma unroll
            for (int mi = 0; mi < 4; mi++)
#pragma unroll
                for (int ni = 0; ni < 4; ni++) {
                    mma16816(acc[mi][ni], a_hi_f[mi], b_hi_f[ni]);
                    mma16816(acc[mi][ni], a_hi_f[mi], b_lo_f[ni]);
                    mma16816(acc[mi][ni], a_lo_f[mi], b_hi_f[ni]);
                }
        }
        __syncthreads();
    }

    // epilogue: c-frag mapping: c0,c1 -> (m=lane/4, n=(lane%4)*2 +0,1), c2,c3 -> m+8
    float* C = (Cid >= 0) ? scratch_resolve(Cid) : Cext;
    const int qrow = lane >> 2, qcol = (lane & 3) * 2;
    const int n_warp0 = bn * 128 + warp_n * 32;
#pragma unroll
    for (int mi = 0; mi < 4; mi++) {
#pragma unroll
        for (int half = 0; half < 2; half++) {
            const int m = bm * 128 + warp_m * 64 + mi * 16 + half * 8 + qrow;
            float* crow = C + (size_t)m * Ntot + n_warp0;
#pragma unroll
            for (int ni = 0; ni < 4; ni++) {
                float x0 = acc[mi][ni][half * 2];
                float x1 = acc[mi][ni][half * 2 + 1];
                const int n = n_warp0 + ni * 8 + qcol;
                if (ACT == 1) {
                    x0 = x0 / (1.0f + expf(-x0));
                    x1 = x1 / (1.0f + expf(-x1));
                } else if (ACT == 2) {
                    float a0 = expf(aux1[n >> 7]);
                    float a1 = expf(aux1[(n + 1) >> 7]);
                    float s0 = x0 + aux2[n], s1 = x1 + aux2[n + 1];
                    s0 = (s0 > 20.0f) ? s0 : log1pf(expf(s0));
                    s1 = (s1 > 20.0f) ? s1 : log1pf(expf(s1));
                    x0 = expf(-a0 * s0); x1 = expf(-a1 * s1);
                } else if (ACT == 3) {
                    x0 = 1.0f / (1.0f + expf(-(x0 + aux1[n])));
                    x1 = 1.0f / (1.0f + expf(-(x1 + aux1[n + 1])));
                }
                float2 o2; o2.x = x0; o2.y = x1;
                *(float2*)(crow + ni * 8 + qcol) = o2;
            }
        }
    }
}

// --------------------------- beta = sigmoid(h @ b_w^T) ---------------------
__global__ __launch_bounds__(512) void beta_kernel(
    const float* __restrict__ H, const float* __restrict__ BW)
{
    float* BETA = scratch_resolve(ID_BETA);
    const int m = blockIdx.x;
    const int w = threadIdx.x >> 5, lane = threadIdx.x & 31;
    const float4* hr = (const float4*)(H + (size_t)m * HIDc);
    const float4* br = (const float4*)(BW + (size_t)w * HIDc);
    float s = 0.f;
#pragma unroll 4
    for (int i = lane; i < HIDc / 4; i += 32) {
        float4 a = hr[i], b = br[i];
        s += a.x * b.x + a.y * b.y + a.z * b.z + a.w * b.w;
    }
#pragma unroll
    for (int off = 16; off > 0; off >>= 1)
        s += __shfl_xor_sync(0xffffffffu, s, off);
    if (lane == 0) BETA[(size_t)m * Hc + w] = 1.0f / (1.0f + expf(-s));
}

// --------------------------- per-head L2 norm (in place) -------------------
__global__ __launch_bounds__(128) void l2norm_kernel(int Xid, float scale)
{
    float* X = scratch_resolve(Xid);
    const int h = blockIdx.x, m = blockIdx.y;
    const int v = threadIdx.x;
    const size_t off = (size_t)m * HIDc + (size_t)h * DKc + v;
    float x = X[off];
    float s = x * x;
#pragma unroll
    for (int o = 16; o > 0; o >>= 1) s += __shfl_xor_sync(0xffffffffu, s, o);
    __shared__ float red[4];
    if ((v & 31) == 0) red[v >> 5] = s;
    __syncthreads();
    float tot = red[0] + red[1] + red[2] + red[3];
    X[off] = x * rsqrtf(tot + 1e-6f) * scale;
}

// ---------- gated RMS norm: og = rms(o)*w*sigf, emitted as bf16 hi/lo ------
__global__ __launch_bounds__(128) void gate_kernel(const float* __restrict__ NW)
{
    const float* O    = scratch_resolve(ID_O);
    const float* SIGF = scratch_resolve(ID_SIGF);
    const int h = blockIdx.x, m = blockIdx.y;
    const int v = threadIdx.x;
    const size_t off = (size_t)m * HIDc + (size_t)h * DVc + v;
    float x = O[off];
    float s = x * x;
#pragma unroll
    for (int o = 16; o > 0; o >>= 1) s += __shfl_xor_sync(0xffffffffu, s, o);
    __shared__ float red[4];
    if ((v & 31) == 0) red[v >> 5] = s;
    __syncthreads();
    float tot = red[0] + red[1] + red[2] + red[3];
    float r = rsqrtf(tot * (1.0f / DVc) + 1e-5f);
    float y = x * r * NW[v] * SIGF[off];
    __nv_bfloat16 hi = __float2bfloat16(y);
    __nv_bfloat16 lo = __float2bfloat16(y - __bfloat162float(hi));
    g_bfpool[OFF_OG_HI + off] = hi;
    g_bfpool[OFF_OG_LO + off] = lo;
}

// ------------------------------ recurrent scan -----------------------------
__global__ __launch_bounds__(128) void scan_kernel(
    const float* __restrict__ S0,
    float* __restrict__ Sout, int writeS)
{
    const float* Q    = scratch_resolve(ID_Q);
    const float* K    = scratch_resolve(ID_K);
    const float* V    = scratch_resolve(ID_V);
    const float* EG   = scratch_resolve(ID_EG);
    const float* BETA = scratch_resolve(ID_BETA);
    float*       O    = scratch_resolve(ID_O);

    const int vh = blockIdx.x, h = blockIdx.y, b = blockIdx.z;
    const int tid = threadIdx.x;
    const int vloc = tid >> 1, khalf = tid & 1;
    const int v = vh * 64 + vloc;
    const int ks = khalf * 64;

    __shared__ float sbuf[3][4][128];   // [stage][k,q,v,eg][128]
    __shared__ float sbeta[3];

    const size_t rowbase = (size_t)b * Tc * HIDc + (size_t)h * DKc;

    ull S[32];
    {
        const float* s0p = S0 + (((size_t)(b * Hc + h) * DKc + ks) * DVc + v);
#pragma unroll
        for (int j2 = 0; j2 < 32; j2++)
            S[j2] = f2pack(s0p[(size_t)(2 * j2) * DVc], s0p[(size_t)(2 * j2 + 1) * DVc]);
    }

    const int grp = tid >> 5, lane = tid & 31;
    const float* srcs[4] = {K, Q, V, EG};

#pragma unroll
    for (int t = 0; t < 2; t++) {
        size_t off = rowbase + (size_t)t * HIDc;
        cp16(&sbuf[t][grp][lane * 4], srcs[grp] + off + lane * 4);
        if (tid == 0) cp4(&sbeta[t], BETA + ((size_t)(b * Tc + t)) * Hc + h);
        cp_commit();
    }

    for (int t = 0; t < Tc; t++) {
        const int nt = t + 2;
        if (nt < Tc) {
            const int st = nt % 3;
            size_t off = rowbase + (size_t)nt * HIDc;
            cp16(&sbuf[st][grp][lane * 4], srcs[grp] + off + lane * 4);
            if (tid == 0) cp4(&sbeta[st], BETA + ((size_t)(b * Tc + nt)) * Hc + h);
        }
        cp_commit();
        cp_wait2();
        __syncthreads();

        const int cb = t % 3;
        const float beta = sbeta[cb];
        const float vv = sbuf[cb][2][v];

        ull k2[32];
        ull kv2 = 0ull;
#pragma unroll
        for (int j2 = 0; j2 < 32; j2++) {
            k2[j2]   = *(const ull*)&sbuf[cb][0][ks + 2 * j2];
            ull eg2  = *(const ull*)&sbuf[cb][3][ks + 2 * j2];
            S[j2] = fmul2(S[j2], eg2);
            kv2 = ffma2(k2[j2], S[j2], kv2);
        }
        float2 kvp = f2unpack(kv2);
        float kv = kvp.x + kvp.y;
        kv += __shfl_xor_sync(0xffffffffu, kv, 1);

        const float delta = (vv - kv) * beta;
        const ull d2 = f2pack(delta, delta);

        ull o2 = 0ull;
#pragma unroll
        for (int j2 = 0; j2 < 32; j2++) {
            S[j2] = ffma2(k2[j2], d2, S[j2]);
            ull q2 = *(const ull*)&sbuf[cb][1][ks + 2 * j2];
            o2 = ffma2(q2, S[j2], o2);
        }
        float2 op = f2unpack(o2);
        float o = op.x + op.y;
        o += __shfl_xor_sync(0xffffffffu, o, 1);
        if (khalf == 0)
            O[rowbase + (size_t)t * HIDc + v] = o;
        __syncthreads();
    }

    if (writeS) {
        float* sp = Sout + (((size_t)(b * Hc + h) * DKc + ks) * DVc + v);
#pragma unroll
        for (int j2 = 0; j2 < 32; j2++) {
            float2 c = f2unpack(S[j2]);
            sp[(size_t)(2 * j2) * DVc]     = c.x;
            sp[(size_t)(2 * j2 + 1) * DVc] = c.y;
        }
    }
}

// ------------------------------ host launcher ------------------------------
extern "C" void kernel_launch(void* const* d_in, const int* in_sizes, int n_in,
                              void* d_out, int out_size)
{
    const float* h      = (const float*)d_in[0];
    const float* S0     = (const float*)d_in[1];
    const float* q_w    = (const float*)d_in[2];
    const float* k_w    = (const float*)d_in[3];
    const float* v_w    = (const float*)d_in[4];
    const float* f_w0   = (const float*)d_in[5];
    const float* f_w1   = (const float*)d_in[6];
    const float* b_w    = (const float*)d_in[7];
    const float* A_log  = (const float*)d_in[8];
    const float* dt_b   = (const float*)d_in[9];
    const float* g_w0   = (const float*)d_in[10];
    const float* g_w1   = (const float*)d_in[11];
    const float* g_b1   = (const float*)d_in[12];
    const float* o_nw   = (const float*)d_in[13];
    const float* o_w    = (const float*)d_in[14];
    float* out = (float*)d_out;

    cudaFuncSetAttribute(mma_gemm<0>, cudaFuncAttributeMaxDynamicSharedMemorySize, GSMEM);
    cudaFuncSetAttribute(mma_gemm<1>, cudaFuncAttributeMaxDynamicSharedMemorySize, GSMEM);
    cudaFuncSetAttribute(mma_gemm<2>, cudaFuncAttributeMaxDynamicSharedMemorySize, GSMEM);
    cudaFuncSetAttribute(mma_gemm<3>, cudaFuncAttributeMaxDynamicSharedMemorySize, GSMEM);

    const dim3 g_big(HIDc / 128, Mc / 128);   // (16, 64)
    const dim3 g_n128(1, Mc / 128);           // (1, 64)

    // ---- split inputs into bf16 hi/lo ----
    split_kernel<<<(Mc * HIDc) / 1024, 256>>>(h,    -1, OFF_HB_HI,  OFF_HB_LO);
    split_kernel<<<(HIDc * HIDc) / 1024, 256>>>(q_w, -1, OFF_WQ_HI,  OFF_WQ_LO);
    split_kernel<<<(HIDc * HIDc) / 1024, 256>>>(k_w, -1, OFF_WK_HI,  OFF_WK_LO);
    split_kernel<<<(HIDc * HIDc) / 1024, 256>>>(v_w, -1, OFF_WV_HI,  OFF_WV_LO);
    split_kernel<<<(HIDc * HIDc) / 1024, 256>>>(o_w, -1, OFF_WO_HI,  OFF_WO_LO);
    split_kernel<<<(128 * HIDc) / 1024, 256>>>(f_w0, -1, OFF_FW0_HI, OFF_FW0_LO);
    split_kernel<<<(128 * HIDc) / 1024, 256>>>(g_w0, -1, OFF_GW0_HI, OFF_GW0_LO);
    split_kernel<<<(HIDc * 128) / 1024, 256>>>(f_w1, -1, OFF_FW1_HI, OFF_FW1_LO);
    split_kernel<<<(HIDc * 128) / 1024, 256>>>(g_w1, -1, OFF_GW1_HI, OFF_GW1_LO);

    // ---- projections (silu fused) ----
    mma_gemm<1><<<g_big, 256, GSMEM>>>(OFF_HB_HI, OFF_HB_LO, OFF_WQ_HI, OFF_WQ_LO,
                                       nullptr, ID_Q, HIDc, HIDc, nullptr, nullptr);
    mma_gemm<1><<<g_big, 256, GSMEM>>>(OFF_HB_HI, OFF_HB_LO, OFF_WK_HI, OFF_WK_LO,
                                       nullptr, ID_K, HIDc, HIDc, nullptr, nullptr);
    mma_gemm<1><<<g_big, 256, GSMEM>>>(OFF_HB_HI, OFF_HB_LO, OFF_WV_HI, OFF_WV_LO,
                                       nullptr, ID_V, HIDc, HIDc, nullptr, nullptr);

    // ---- gate: eg = exp(-exp(A_log)*softplus((h@f_w0^T)@f_w1^T + dt_bias)) ----
    mma_gemm<0><<<g_n128, 256, GSMEM>>>(OFF_HB_HI, OFF_HB_LO, OFF_FW0_HI, OFF_FW0_LO,
                                        nullptr, ID_TMP, 128, HIDc, nullptr, nullptr);
    split_kernel<<<(Mc * 128) / 1024, 256>>>(nullptr, ID_TMP, OFF_TMP_HI, OFF_TMP_LO);
    mma_gemm<2><<<g_big, 256, GSMEM>>>(OFF_TMP_HI, OFF_TMP_LO, OFF_FW1_HI, OFF_FW1_LO,
                                       nullptr, ID_EG, HIDc, 128, A_log, dt_b);

    // ---- beta + l2 norms ----
    beta_kernel<<<Mc, 512>>>(h, b_w);
    l2norm_kernel<<<dim3(Hc, Mc), 128>>>(ID_Q, 0.08838834764831845f);
    l2norm_kernel<<<dim3(Hc, Mc), 128>>>(ID_K, 1.0f);

    // ---- output gate factor: sigf = sigmoid((h@g_w0^T)@g_w1^T + g_b1) ----
    mma_gemm<0><<<g_n128, 256, GSMEM>>>(OFF_HB_HI, OFF_HB_LO, OFF_GW0_HI, OFF_GW0_LO,
                                        nullptr, ID_TMP, 128, HIDc, nullptr, nullptr);
    split_kernel<<<(Mc * 128) / 1024, 256>>>(nullptr, ID_TMP, OFF_TMP_HI, OFF_TMP_LO);
    mma_gemm<3><<<g_big, 256, GSMEM>>>(OFF_TMP_HI, OFF_TMP_LO, OFF_GW1_HI, OFF_GW1_LO,
                                       nullptr, ID_SIGF, HIDc, 128, g_b1, nullptr);

    // ---- recurrent scan ----
    const size_t out_elems = (size_t)Mc * HIDc;                 // 16,777,216
    const size_t s_elems   = (size_t)Bc * Hc * DKc * DVc;       //  1,048,576
    const int writeS = ((size_t)out_size >= out_elems + s_elems) ? 1 : 0;
    scan_kernel<<<dim3(2, Hc, Bc), 128>>>(S0, out + out_elems, writeS);

    // ---- gated rms norm (emits bf16 hi/lo) + final projection ----
    gate_kernel<<<dim3(Hc, Mc), 128>>>(o_nw);
    mma_gemm<0><<<g_big, 256, GSMEM>>>(OFF_OG_HI, OFF_OG_LO, OFF_WO_HI, OFF_WO_LO,
                                       out, -1, HIDc, HIDc, nullptr, nullptr);
}